// round 8
// baseline (speedup 1.0000x reference)
#include <cuda_runtime.h>

// SigNet: depth-4 path signature (C=8 incl. time) + linear head.
// K1: 8-way segmented Chen scan with d-axis f32x2 packing (FFMA2), factored
//     updates, duplicated-v smem table for splat-free packed operands,
//     in-smem tree combine. No dynamic register-array indexing.
// K2: split-k GEMM (KSPLIT=21).  K3: reduce + bias.

#define NB      128
#define SLEN    1024
#define NSEG    8
#define SEG     128
#define CIN     7
#define SIGCH   4680          // 8 + 64 + 512 + 4096
#define YSTRIDE 4704
#define DOUT    256
#define KSPLIT  21
#define KCHUNK  224           // 21*224 = 4704

typedef unsigned long long u64;

__device__ __forceinline__ u64 fma2(u64 a, u64 b, u64 c){ u64 d; asm("fma.rn.f32x2 %0,%1,%2,%3;" : "=l"(d) : "l"(a),"l"(b),"l"(c)); return d; }
__device__ __forceinline__ u64 mul2(u64 a, u64 b){ u64 d; asm("mul.rn.f32x2 %0,%1,%2;" : "=l"(d) : "l"(a),"l"(b)); return d; }
__device__ __forceinline__ u64 add2(u64 a, u64 b){ u64 d; asm("add.rn.f32x2 %0,%1,%2;" : "=l"(d) : "l"(a),"l"(b)); return d; }
__device__ __forceinline__ float2 unpack2(u64 a){ float2 f; asm("mov.b64 {%0,%1},%2;" : "=f"(f.x),"=f"(f.y) : "l"(a)); return f; }
__device__ __forceinline__ u64 pack2(float x, float y){ u64 d; asm("mov.b64 %0,{%1,%2};" : "=l"(d) : "f"(x),"f"(y)); return d; }

__device__ float g_y[NB * YSTRIDE];
__device__ float g_part[KSPLIT * NB * DOUT];

// smem: vs[1024][8] (8192 fl) + vdup[1024][16] (16384 fl) = 24576 fl during scan;
// then reused as T[8][4680] = 37440 floats during combine.
#define OFF_VDUP 8192
#define SMEM_FLOATS (NSEG * SIGCH)     // 37440 floats = 149760 B

// ---- Chen combine pieces (X = A o B, A earlier in time) ----
__device__ __forceinline__ void chen_l4(const float* __restrict__ A,
                                        const float* __restrict__ B,
                                        float* __restrict__ X, int lane, int nth)
{
    for (int e = lane; e < 4096; e += nth) {
        float v = A[584 + e] + B[584 + e];
        v = fmaf(A[e >> 9],        B[72 + (e & 511)], v);
        v = fmaf(A[8 + (e >> 6)],  B[8  + (e & 63)],  v);
        v = fmaf(A[72 + (e >> 3)], B[e & 7],          v);
        X[584 + e] = v;
    }
}
__device__ __forceinline__ void chen_l3(const float* __restrict__ A,
                                        const float* __restrict__ B,
                                        float* __restrict__ X, int lane, int nth)
{
    for (int e = lane; e < 512; e += nth) {
        float v = A[72 + e] + B[72 + e];
        v = fmaf(A[e >> 6],       B[8 + (e & 63)], v);
        v = fmaf(A[8 + (e >> 3)], B[e & 7],        v);
        X[72 + e] = v;
    }
}
__device__ __forceinline__ void chen_inplace(float* __restrict__ A,
                                             const float* __restrict__ B,
                                             int lane, int nth)
{
    chen_l4(A, B, A, lane, nth);      // reads A[0..584), writes A[584..)
    __syncthreads();
    chen_l3(A, B, A, lane, nth);      // reads A[0..72), writes A[72..584)
    float v2 = 0.0f, v1 = 0.0f;
    if (lane < 64) v2 = A[8 + lane] + B[8 + lane] + A[lane >> 3] * B[lane & 7];
    if (lane < 8)  v1 = A[lane] + B[lane];
    __syncthreads();
    if (lane < 64) A[8 + lane] = v2;
    if (lane < 8)  A[lane] = v1;
}

// ---------------------------------------------------------------------------
// Kernel 1: segmented scan. 1 CTA/batch, 512 threads = 8 groups x 64.
// Thread u=tid&63 owns (a,b)=(u>>3,u&7); sig4 packed over d-pairs (32 u64),
// K/s3/scalar chain in duplicated f32x2 form.
// ---------------------------------------------------------------------------
__global__ __launch_bounds__(512, 1) void sig_scan_kernel(const float* __restrict__ inp)
{
    extern __shared__ float sm[];
    const int b   = blockIdx.x;
    const int tid = threadIdx.x;

    // Build increments (packed + duplicated tables).
    const float dt = 1.0f / 1023.0f;
    const float* x = inp + (size_t)b * SLEN * CIN;
    for (int i = tid; i < SLEN * CIN; i += 512) {
        int t = i / CIN, c = i - t * CIN;
        float cur  = x[i];
        float prev = (t == 0) ? 0.0f : x[i - CIN];
        float d = cur - prev;
        sm[t * 8 + c + 1] = d;
        sm[OFF_VDUP + t * 16 + 2 * (c + 1)]     = d;
        sm[OFF_VDUP + t * 16 + 2 * (c + 1) + 1] = d;
    }
    for (int t = tid; t < SLEN; t += 512) {
        float d = (t == 0) ? 0.0f : dt;
        sm[t * 8] = d;
        sm[OFF_VDUP + t * 16]     = d;
        sm[OFF_VDUP + t * 16 + 1] = d;
    }
    __syncthreads();

    const int g  = tid >> 6;          // segment 0..7
    const int u  = tid & 63;          // (a,b)
    const int a  = u >> 3;
    const int bb = u & 7;

    u64 s1d = 0ull, s2d = 0ull;
    u64 s3d[8];
    u64 sig4[32];                     // [c][dpair]
#pragma unroll
    for (int i = 0; i < 8; i++) s3d[i] = 0ull;
#pragma unroll
    for (int i = 0; i < 32; i++) sig4[i] = 0ull;

    const u64 C24 = pack2(1.0f/24.0f, 1.0f/24.0f);
    const u64 C6  = pack2(1.0f/6.0f,  1.0f/6.0f);
    const u64 CH  = pack2(0.5f, 0.5f);

    const float* vrow = sm + g * SEG * 8;
    const float* drow = sm + OFF_VDUP + g * SEG * 16;

#pragma unroll 1
    for (int t = 0; t < SEG; t++) {
        // Packed d-pairs straight from LDS.128 (already FFMA2-ready).
        ulonglong2 p0 = *(const ulonglong2*)(vrow + t * 8);      // (v0,v1)(v2,v3)
        ulonglong2 p1 = *(const ulonglong2*)(vrow + t * 8 + 4);  // (v4,v5)(v6,v7)
        // Duplicated (va,va),(vb,vb) for the scalar chain (runtime offset -> LDS).
        u64 vad = *(const u64*)(drow + t * 16 + 2 * a);
        u64 vbd = *(const u64*)(drow + t * 16 + 2 * bb);

        // Scalar recurrences, duplicated in both halves. Uses OLD s1,s2.
        u64 t6d = fma2(s1d, C6, mul2(vad, C24));   // va/24 + s1/6
        u64 uud = fma2(s1d, CH, mul2(vad, C6));    // va/6  + s1/2
        u64 m1d = fma2(vbd, t6d, mul2(s2d, CH));   // vb*t6 + s2/2
        u64 m2d = fma2(vbd, uud, s2d);             // vb*uu + s2
        s2d = fma2(vbd, fma2(vad, CH, s1d), s2d);  // s2 + va*vb/2 + s1*vb
        s1d = add2(s1d, vad);

#define CBLOCK(c)                                                          \
        {                                                                  \
            u64 vdc = *(const u64*)(drow + t * 16 + 2 * (c));              \
            u64 K   = fma2(vdc, m1d, s3d[c]);                              \
            s3d[c]  = fma2(vdc, m2d, s3d[c]);                              \
            sig4[(c)*4+0] = fma2(K, p0.x, sig4[(c)*4+0]);                  \
            sig4[(c)*4+1] = fma2(K, p0.y, sig4[(c)*4+1]);                  \
            sig4[(c)*4+2] = fma2(K, p1.x, sig4[(c)*4+2]);                  \
            sig4[(c)*4+3] = fma2(K, p1.y, sig4[(c)*4+3]);                  \
        }
        CBLOCK(0) CBLOCK(1) CBLOCK(2) CBLOCK(3)
        CBLOCK(4) CBLOCK(5) CBLOCK(6) CBLOCK(7)
#undef CBLOCK
    }

    // All scan reads of sm done -> safe to overwrite with T[8][4680].
    __syncthreads();

    float* P = sm + g * SIGCH;
#pragma unroll
    for (int c = 0; c < 8; c++) {
#pragma unroll
        for (int dp = 0; dp < 4; dp++) {
            float2 f = unpack2(sig4[c * 4 + dp]);
            P[584 + u * 64 + c * 8 + 2 * dp]     = f.x;
            P[584 + u * 64 + c * 8 + 2 * dp + 1] = f.y;
        }
        P[72 + u * 8 + c] = unpack2(s3d[c]).x;
    }
    P[8 + u] = unpack2(s2d).x;
    if (bb == 0) P[a] = unpack2(s1d).x;
    __syncthreads();

    // Round 1: 4 parallel in-place combines, 128 threads each.
    {
        int pair = tid >> 7, lane = tid & 127;
        float* A = sm + (2 * pair) * SIGCH;
        const float* B = A + SIGCH;
        chen_inplace(A, B, lane, 128);
    }
    __syncthreads();
    // Round 2: 2 parallel in-place combines, 256 threads each.
    {
        int pair = tid >> 8, lane = tid & 255;
        float* A = sm + (4 * pair) * SIGCH;
        const float* B = A + 2 * SIGCH;
        chen_inplace(A, B, lane, 256);
    }
    __syncthreads();
    // Round 3: final combine straight to global.
    {
        const float* A = sm;
        const float* B = sm + 4 * SIGCH;
        float* y = g_y + (size_t)b * YSTRIDE;
        chen_l4(A, B, y, tid, 512);
        chen_l3(A, B, y, tid, 512);
        if (tid < 64) y[8 + tid] = A[8 + tid] + B[8 + tid] + A[tid >> 3] * B[tid & 7];
        if (tid < 8)  y[tid] = A[tid] + B[tid];
        if (tid < YSTRIDE - SIGCH) y[SIGCH + tid] = 0.0f;
    }
}

// ---------------------------------------------------------------------------
// Kernel 2: split-k GEMM partials (R6-proven version). grid = (16, KSPLIT).
// ---------------------------------------------------------------------------
__global__ __launch_bounds__(256, 1) void gemm_part_kernel(const float* __restrict__ W)
{
    __shared__ float ys[128][32];
    __shared__ float ws[16][33];

    const int tid = threadIdx.x;
    const int cg = blockIdx.x;
    const int sp = blockIdx.y;
    const int kbase = sp * KCHUNK;

    const int cp = tid & 7;        // col pair: cols 2cp, 2cp+1
    const int rg = tid >> 3;       // rows rg + 32*j

    float acc00 = 0.f, acc01 = 0.f, acc02 = 0.f, acc03 = 0.f;
    float acc10 = 0.f, acc11 = 0.f, acc12 = 0.f, acc13 = 0.f;

    for (int kc = 0; kc < KCHUNK; kc += 32) {
        const int k0 = kbase + kc;
#pragma unroll
        for (int ii = 0; ii < 4; ii++) {
            int lin = tid + 256 * ii;
            int r = lin >> 3, seg = lin & 7;
            float4 val = *(const float4*)&g_y[r * YSTRIDE + k0 + seg * 4];
            *(float4*)&ys[r][seg * 4] = val;
        }
#pragma unroll
        for (int ii = 0; ii < 2; ii++) {
            int lin = tid + 256 * ii;
            int r = lin >> 5, cc = lin & 31;
            int k = k0 + cc;
            ws[r][cc] = (k < SIGCH) ? W[(cg * 16 + r) * SIGCH + k] : 0.0f;
        }
        __syncthreads();
#pragma unroll
        for (int kk = 0; kk < 32; kk += 2) {
            float2 w0 = *(const float2*)&ws[2 * cp][kk];
            float2 w1 = *(const float2*)&ws[2 * cp + 1][kk];
            float2 y0 = *(const float2*)&ys[rg][kk];
            float2 y1 = *(const float2*)&ys[rg + 32][kk];
            float2 y2 = *(const float2*)&ys[rg + 64][kk];
            float2 y3 = *(const float2*)&ys[rg + 96][kk];
            acc00 = fmaf(y0.x, w0.x, acc00); acc00 = fmaf(y0.y, w0.y, acc00);
            acc01 = fmaf(y1.x, w0.x, acc01); acc01 = fmaf(y1.y, w0.y, acc01);
            acc02 = fmaf(y2.x, w0.x, acc02); acc02 = fmaf(y2.y, w0.y, acc02);
            acc03 = fmaf(y3.x, w0.x, acc03); acc03 = fmaf(y3.y, w0.y, acc03);
            acc10 = fmaf(y0.x, w1.x, acc10); acc10 = fmaf(y0.y, w1.y, acc10);
            acc11 = fmaf(y1.x, w1.x, acc11); acc11 = fmaf(y1.y, w1.y, acc11);
            acc12 = fmaf(y2.x, w1.x, acc12); acc12 = fmaf(y2.y, w1.y, acc12);
            acc13 = fmaf(y3.x, w1.x, acc13); acc13 = fmaf(y3.y, w1.y, acc13);
        }
        __syncthreads();
    }

    const int col0 = cg * 16 + 2 * cp;
    float* p = g_part + (size_t)sp * NB * DOUT;
    p[(rg +  0) * DOUT + col0]     = acc00;
    p[(rg + 32) * DOUT + col0]     = acc01;
    p[(rg + 64) * DOUT + col0]     = acc02;
    p[(rg + 96) * DOUT + col0]     = acc03;
    p[(rg +  0) * DOUT + col0 + 1] = acc10;
    p[(rg + 32) * DOUT + col0 + 1] = acc11;
    p[(rg + 64) * DOUT + col0 + 1] = acc12;
    p[(rg + 96) * DOUT + col0 + 1] = acc13;
}

// ---------------------------------------------------------------------------
__global__ void reduce_bias_kernel(const float* __restrict__ bias, float* __restrict__ out)
{
    int idx = blockIdx.x * 256 + threadIdx.x;
    float v = bias[idx & (DOUT - 1)];
#pragma unroll
    for (int s = 0; s < KSPLIT; s++)
        v += g_part[s * NB * DOUT + idx];
    out[idx] = v;
}

// ---------------------------------------------------------------------------
extern "C" void kernel_launch(void* const* d_in, const int* in_sizes, int n_in,
                              void* d_out, int out_size)
{
    (void)in_sizes; (void)n_in; (void)out_size;
    const float* inp  = (const float*)d_in[0];   // (128,1024,7)
    const float* W    = (const float*)d_in[1];   // (256,4680)
    const float* bias = (const float*)d_in[2];   // (256,)
    float* out = (float*)d_out;                  // (128,256)

    const int smem_bytes = SMEM_FLOATS * sizeof(float);   // 149760
    cudaFuncSetAttribute(sig_scan_kernel,
                         cudaFuncAttributeMaxDynamicSharedMemorySize, smem_bytes);

    sig_scan_kernel<<<NB, 512, smem_bytes>>>(inp);
    dim3 g2(16, KSPLIT);
    gemm_part_kernel<<<g2, 256>>>(W);
    reduce_bias_kernel<<<NB, 256>>>(bias, out);
}

// round 9
// speedup vs baseline: 1.3987x; 1.3987x over previous
#include <cuda_runtime.h>

// SigNet: depth-4 path signature (C=8 incl. time) + linear head.
// K1: 8-way segmented scalar Chen scan (R6 structure) + FFMA-imm on the
//     constant time-channel increment (dt literal, 127/128 steps) +
//     in-smem tree combine. No dynamic register-array indexing, no f32x2.
// K2: split-k GEMM, 296-CTA balanced wave (8 cg x KSPLIT 37), 16 accums/thread,
//     transposed W tile for LDS.128 broadcast.
// K3: reduce + bias.

#define NB      128
#define SLEN    1024
#define NSEG    8
#define SEG     128
#define CIN     7
#define SIGCH   4680          // 8 + 64 + 512 + 4096
#define YSTRIDE 4736          // 37*128; pad [4680,4736) stays zero
#define DOUT    256
#define KSPLIT  37
#define KCHUNK  128           // 37*128 = 4736
#define DT      (1.0f/1023.0f)

__device__ float g_y[NB * YSTRIDE];
__device__ float g_part[KSPLIT * NB * DOUT];

// smem: vs[1024][8] = 8192 floats, then reused as T[8][4680] = 37440 floats.
#define SMEM_FLOATS (NSEG * SIGCH)     // 37440 floats = 149760 B

// ---- Chen combine pieces (X = A o B, A earlier in time) ----
__device__ __forceinline__ void chen_l4(const float* __restrict__ A,
                                        const float* __restrict__ B,
                                        float* __restrict__ X, int lane, int nth)
{
    for (int e = lane; e < 4096; e += nth) {
        float v = A[584 + e] + B[584 + e];
        v = fmaf(A[e >> 9],        B[72 + (e & 511)], v);
        v = fmaf(A[8 + (e >> 6)],  B[8  + (e & 63)],  v);
        v = fmaf(A[72 + (e >> 3)], B[e & 7],          v);
        X[584 + e] = v;
    }
}
__device__ __forceinline__ void chen_l3(const float* __restrict__ A,
                                        const float* __restrict__ B,
                                        float* __restrict__ X, int lane, int nth)
{
    for (int e = lane; e < 512; e += nth) {
        float v = A[72 + e] + B[72 + e];
        v = fmaf(A[e >> 6],       B[8 + (e & 63)], v);
        v = fmaf(A[8 + (e >> 3)], B[e & 7],        v);
        X[72 + e] = v;
    }
}
__device__ __forceinline__ void chen_inplace(float* __restrict__ A,
                                             const float* __restrict__ B,
                                             int lane, int nth)
{
    chen_l4(A, B, A, lane, nth);      // reads A[0..584), writes A[584..)
    __syncthreads();
    chen_l3(A, B, A, lane, nth);      // reads A[0..72), writes A[72..584)
    float v2 = 0.0f, v1 = 0.0f;
    if (lane < 64) v2 = A[8 + lane] + B[8 + lane] + A[lane >> 3] * B[lane & 7];
    if (lane < 8)  v1 = A[lane] + B[lane];
    __syncthreads();
    if (lane < 64) A[8 + lane] = v2;
    if (lane < 8)  A[lane] = v1;
}

// One scan step. V0X is the channel-0 increment: a register in the peeled
// first step, the literal DT afterwards (FFMA-imm, rt=1 on sm_100a).
// Uses v0,v1 (float4), va, vb, s1, s2, s3[], sig4[] from enclosing scope.
#define SCAN_STEP(V0X)                                                       \
    {                                                                        \
        float t6 = fmaf(s1, inv6, va * inv24);   /* va/24 + s1/6 */          \
        float uu = fmaf(s1, 0.5f, va * inv6);    /* va/6  + s1/2 */          \
        float m1 = fmaf(vb, t6, s2 * 0.5f);      /* vb*t6 + s2/2 */          \
        float m2 = fmaf(vb, uu, s2);             /* vb*uu + s2   */          \
        s2 = fmaf(vb, fmaf(va, 0.5f, s1), s2);                               \
        s1 += va;                                                            \
        float K0 = fmaf((V0X), m1, s3[0]);  s3[0] = fmaf((V0X), m2, s3[0]);  \
        float K1 = fmaf(v0.y,  m1, s3[1]);  s3[1] = fmaf(v0.y,  m2, s3[1]);  \
        float K2 = fmaf(v0.z,  m1, s3[2]);  s3[2] = fmaf(v0.z,  m2, s3[2]);  \
        float K3 = fmaf(v0.w,  m1, s3[3]);  s3[3] = fmaf(v0.w,  m2, s3[3]);  \
        float K4 = fmaf(v1.x,  m1, s3[4]);  s3[4] = fmaf(v1.x,  m2, s3[4]);  \
        float K5 = fmaf(v1.y,  m1, s3[5]);  s3[5] = fmaf(v1.y,  m2, s3[5]);  \
        float K6 = fmaf(v1.z,  m1, s3[6]);  s3[6] = fmaf(v1.z,  m2, s3[6]);  \
        float K7 = fmaf(v1.w,  m1, s3[7]);  s3[7] = fmaf(v1.w,  m2, s3[7]);  \
        SIG4ROW(0, K0) SIG4ROW(1, K1) SIG4ROW(2, K2) SIG4ROW(3, K3)         \
        SIG4ROW(4, K4) SIG4ROW(5, K5) SIG4ROW(6, K6) SIG4ROW(7, K7)         \
    }
#define SIG4ROW(c, Kc)                                                       \
        sig4[c*8+0] = fmaf(Kc, (V0X_D), sig4[c*8+0]);                        \
        sig4[c*8+1] = fmaf(Kc, v0.y, sig4[c*8+1]);                           \
        sig4[c*8+2] = fmaf(Kc, v0.z, sig4[c*8+2]);                           \
        sig4[c*8+3] = fmaf(Kc, v0.w, sig4[c*8+3]);                           \
        sig4[c*8+4] = fmaf(Kc, v1.x, sig4[c*8+4]);                           \
        sig4[c*8+5] = fmaf(Kc, v1.y, sig4[c*8+5]);                           \
        sig4[c*8+6] = fmaf(Kc, v1.z, sig4[c*8+6]);                           \
        sig4[c*8+7] = fmaf(Kc, v1.w, sig4[c*8+7]);

// ---------------------------------------------------------------------------
// Kernel 1: segmented scan. 1 CTA/batch, 512 threads = 8 groups x 64.
// Thread u=tid&63 owns (a,b)=(u>>3,u&7): all 8 c, all 8 d (64 L4 accumulators).
// ---------------------------------------------------------------------------
__global__ __launch_bounds__(512, 1) void sig_scan_kernel(const float* __restrict__ inp)
{
    extern __shared__ float sm[];
    const int b   = blockIdx.x;
    const int tid = threadIdx.x;

    // Build increments into sm[0..8192). Basepoint 0: first inc = first sample.
    const float* x = inp + (size_t)b * SLEN * CIN;
    for (int i = tid; i < SLEN * CIN; i += 512) {
        int t = i / CIN, c = i - t * CIN;
        float cur  = x[i];
        float prev = (t == 0) ? 0.0f : x[i - CIN];
        sm[t * 8 + c + 1] = cur - prev;
    }
    for (int t = tid; t < SLEN; t += 512)
        sm[t * 8] = (t == 0) ? 0.0f : DT;
    __syncthreads();

    const int g  = tid >> 6;          // segment 0..7
    const int u  = tid & 63;          // (a,b)
    const int a  = u >> 3;
    const int bb = u & 7;

    float s1 = 0.0f, s2 = 0.0f;
    float s3[8];
    float sig4[64];
#pragma unroll
    for (int i = 0; i < 8; i++) s3[i] = 0.0f;
#pragma unroll
    for (int i = 0; i < 64; i++) sig4[i] = 0.0f;

    const float inv24 = 1.0f / 24.0f;
    const float inv6  = 1.0f / 6.0f;
    const float* vrow = sm + g * SEG * 8;

    // Peeled first step: channel-0 value from memory (0 for segment 0, DT else).
    {
        float4 v0 = *(const float4*)&vrow[0];
        float4 v1 = *(const float4*)&vrow[4];
        float va = vrow[a];
        float vb = vrow[bb];
#define V0X_D v0.x
        SCAN_STEP(v0.x)
#undef V0X_D
    }
    // Remaining 127 steps: channel-0 increment is the literal DT -> FFMA-imm.
#pragma unroll 1
    for (int t = 1; t < SEG; t++) {
        const float* q = vrow + t * 8;
        float4 v0 = *(const float4*)q;
        float4 v1 = *(const float4*)(q + 4);
        float va = q[a];
        float vb = q[bb];
#define V0X_D DT
        SCAN_STEP(DT)
#undef V0X_D
    }

    // All scan reads of sm done -> safe to overwrite with T[8][4680].
    __syncthreads();

    float* P = sm + g * SIGCH;
#pragma unroll
    for (int c = 0; c < 8; c++) {
#pragma unroll
        for (int d = 0; d < 8; d++)
            P[584 + u * 64 + c * 8 + d] = sig4[c * 8 + d];
        P[72 + u * 8 + c] = s3[c];
    }
    P[8 + u] = s2;
    if (bb == 0) P[a] = s1;
    __syncthreads();

    // Round 1: 4 parallel in-place combines, 128 threads each.
    {
        int pair = tid >> 7, lane = tid & 127;
        float* A = sm + (2 * pair) * SIGCH;
        const float* B = A + SIGCH;
        chen_inplace(A, B, lane, 128);
    }
    __syncthreads();
    // Round 2: 2 parallel in-place combines, 256 threads each.
    {
        int pair = tid >> 8, lane = tid & 255;
        float* A = sm + (4 * pair) * SIGCH;
        const float* B = A + 2 * SIGCH;
        chen_inplace(A, B, lane, 256);
    }
    __syncthreads();
    // Round 3: final combine straight to global.
    {
        const float* A = sm;
        const float* B = sm + 4 * SIGCH;
        float* y = g_y + (size_t)b * YSTRIDE;
        chen_l4(A, B, y, tid, 512);
        chen_l3(A, B, y, tid, 512);
        if (tid < 64) y[8 + tid] = A[8 + tid] + B[8 + tid] + A[tid >> 3] * B[tid & 7];
        if (tid < 8)  y[tid] = A[tid] + B[tid];
        if (tid < YSTRIDE - SIGCH) y[SIGCH + tid] = 0.0f;   // 56 pad elems
    }
}

// ---------------------------------------------------------------------------
// Kernel 2: split-k GEMM partials. grid = (8 col-groups, KSPLIT=37) = 296 CTAs
// = exactly 2 resident CTAs on each of 148 SMs (one balanced wave).
// CTA: 128 batch-rows x 32 out-cols over 128 of k. 256 threads, 16 accums.
// ws stored transposed [k][col] so the inner loop reads one LDS.128 per kk
// (broadcast across row-groups); 36-float pitch keeps everything conflict-free.
// ---------------------------------------------------------------------------
__global__ __launch_bounds__(256, 2) void gemm_part_kernel(const float* __restrict__ W)
{
    __shared__ float ys[128][36];
    __shared__ float ws[32][36];    // [k][col]

    const int tid = threadIdx.x;
    const int cg = blockIdx.x;      // cols cg*32 .. cg*32+31
    const int sp = blockIdx.y;      // k in [sp*128, sp*128+128)
    const int kbase = sp * KCHUNK;

    const int cp = tid & 7;         // cols 4cp .. 4cp+3
    const int rg = tid >> 3;        // rows rg + 32*j, j<4

    float acc[4][4];
#pragma unroll
    for (int i = 0; i < 4; i++)
#pragma unroll
        for (int j = 0; j < 4; j++) acc[i][j] = 0.0f;

    for (int kc = 0; kc < KCHUNK; kc += 32) {
        const int k0 = kbase + kc;
        // y tile: 128 x 32
#pragma unroll
        for (int ii = 0; ii < 4; ii++) {
            int lin = tid + 256 * ii;
            int r = lin >> 3, seg = lin & 7;
            float4 val = *(const float4*)&g_y[r * YSTRIDE + k0 + seg * 4];
            *(float4*)&ys[r][seg * 4] = val;
        }
        // W tile transposed: ws[k][col] = W[cg*32+col][k0+k]; guard k >= SIGCH.
#pragma unroll
        for (int ii = 0; ii < 4; ii++) {
            int lin = tid + 256 * ii;        // 0..1023
            int col = lin >> 5, k = lin & 31;
            int kg = k0 + k;
            ws[k][col] = (kg < SIGCH) ? W[(cg * 32 + col) * SIGCH + kg] : 0.0f;
        }
        __syncthreads();
#pragma unroll
        for (int kk = 0; kk < 32; kk += 2) {
            float4 wA = *(const float4*)&ws[kk][4 * cp];
            float4 wB = *(const float4*)&ws[kk + 1][4 * cp];
            float2 y0 = *(const float2*)&ys[rg][kk];
            float2 y1 = *(const float2*)&ys[rg + 32][kk];
            float2 y2 = *(const float2*)&ys[rg + 64][kk];
            float2 y3 = *(const float2*)&ys[rg + 96][kk];
            acc[0][0] = fmaf(y0.x, wA.x, acc[0][0]); acc[0][0] = fmaf(y0.y, wB.x, acc[0][0]);
            acc[0][1] = fmaf(y0.x, wA.y, acc[0][1]); acc[0][1] = fmaf(y0.y, wB.y, acc[0][1]);
            acc[0][2] = fmaf(y0.x, wA.z, acc[0][2]); acc[0][2] = fmaf(y0.y, wB.z, acc[0][2]);
            acc[0][3] = fmaf(y0.x, wA.w, acc[0][3]); acc[0][3] = fmaf(y0.y, wB.w, acc[0][3]);
            acc[1][0] = fmaf(y1.x, wA.x, acc[1][0]); acc[1][0] = fmaf(y1.y, wB.x, acc[1][0]);
            acc[1][1] = fmaf(y1.x, wA.y, acc[1][1]); acc[1][1] = fmaf(y1.y, wB.y, acc[1][1]);
            acc[1][2] = fmaf(y1.x, wA.z, acc[1][2]); acc[1][2] = fmaf(y1.y, wB.z, acc[1][2]);
            acc[1][3] = fmaf(y1.x, wA.w, acc[1][3]); acc[1][3] = fmaf(y1.y, wB.w, acc[1][3]);
            acc[2][0] = fmaf(y2.x, wA.x, acc[2][0]); acc[2][0] = fmaf(y2.y, wB.x, acc[2][0]);
            acc[2][1] = fmaf(y2.x, wA.y, acc[2][1]); acc[2][1] = fmaf(y2.y, wB.y, acc[2][1]);
            acc[2][2] = fmaf(y2.x, wA.z, acc[2][2]); acc[2][2] = fmaf(y2.y, wB.z, acc[2][2]);
            acc[2][3] = fmaf(y2.x, wA.w, acc[2][3]); acc[2][3] = fmaf(y2.y, wB.w, acc[2][3]);
            acc[3][0] = fmaf(y3.x, wA.x, acc[3][0]); acc[3][0] = fmaf(y3.y, wB.x, acc[3][0]);
            acc[3][1] = fmaf(y3.x, wA.y, acc[3][1]); acc[3][1] = fmaf(y3.y, wB.y, acc[3][1]);
            acc[3][2] = fmaf(y3.x, wA.z, acc[3][2]); acc[3][2] = fmaf(y3.y, wB.z, acc[3][2]);
            acc[3][3] = fmaf(y3.x, wA.w, acc[3][3]); acc[3][3] = fmaf(y3.y, wB.w, acc[3][3]);
        }
        __syncthreads();
    }

    const int col0 = cg * 32 + 4 * cp;
    float* p = g_part + (size_t)sp * NB * DOUT;
#pragma unroll
    for (int i = 0; i < 4; i++) {
        float4 v = make_float4(acc[i][0], acc[i][1], acc[i][2], acc[i][3]);
        *(float4*)&p[(rg + 32 * i) * DOUT + col0] = v;
    }
}

// ---------------------------------------------------------------------------
__global__ void reduce_bias_kernel(const float* __restrict__ bias, float* __restrict__ out)
{
    int idx = blockIdx.x * 256 + threadIdx.x;
    float v = bias[idx & (DOUT - 1)];
#pragma unroll
    for (int s = 0; s < KSPLIT; s++)
        v += g_part[s * NB * DOUT + idx];
    out[idx] = v;
}

// ---------------------------------------------------------------------------
extern "C" void kernel_launch(void* const* d_in, const int* in_sizes, int n_in,
                              void* d_out, int out_size)
{
    (void)in_sizes; (void)n_in; (void)out_size;
    const float* inp  = (const float*)d_in[0];   // (128,1024,7)
    const float* W    = (const float*)d_in[1];   // (256,4680)
    const float* bias = (const float*)d_in[2];   // (256,)
    float* out = (float*)d_out;                  // (128,256)

    const int smem_bytes = SMEM_FLOATS * sizeof(float);   // 149760
    cudaFuncSetAttribute(sig_scan_kernel,
                         cudaFuncAttributeMaxDynamicSharedMemorySize, smem_bytes);

    sig_scan_kernel<<<NB, 512, smem_bytes>>>(inp);
    dim3 g2(8, KSPLIT);
    gemm_part_kernel<<<g2, 256>>>(W);
    reduce_bias_kernel<<<NB, 256>>>(bias, out);
}

// round 10
// speedup vs baseline: 1.5517x; 1.1094x over previous
#include <cuda_runtime.h>

// SigNet: depth-4 path signature (C=8 incl. time) + linear head.
// K1: R6-exact scan — 8-way segmented scalar Chen scan (factored updates),
//     in-smem tree combine. No peeling, no f32x2, no dynamic reg indexing.
// K2: R9-exact tail — split-k GEMM, 296-CTA balanced wave (8 cg x KSPLIT 37),
//     16 accums/thread, transposed W tile.  K3: reduce + bias.

#define NB      128
#define SLEN    1024
#define NSEG    8
#define SEG     128
#define CIN     7
#define SIGCH   4680          // 8 + 64 + 512 + 4096
#define YSTRIDE 4736          // 37*128; pad [4680,4736) stays zero
#define DOUT    256
#define KSPLIT  37
#define KCHUNK  128           // 37*128 = 4736

__device__ float g_y[NB * YSTRIDE];
__device__ float g_part[KSPLIT * NB * DOUT];

// smem: vs[1024][8] = 8192 floats, then reused as T[8][4680] = 37440 floats.
#define SMEM_FLOATS (NSEG * SIGCH)     // 37440 floats = 149760 B

// ---- Chen combine pieces (X = A o B, A earlier in time) ----
__device__ __forceinline__ void chen_l4(const float* __restrict__ A,
                                        const float* __restrict__ B,
                                        float* __restrict__ X, int lane, int nth)
{
    for (int e = lane; e < 4096; e += nth) {
        float v = A[584 + e] + B[584 + e];
        v = fmaf(A[e >> 9],        B[72 + (e & 511)], v);
        v = fmaf(A[8 + (e >> 6)],  B[8  + (e & 63)],  v);
        v = fmaf(A[72 + (e >> 3)], B[e & 7],          v);
        X[584 + e] = v;
    }
}
__device__ __forceinline__ void chen_l3(const float* __restrict__ A,
                                        const float* __restrict__ B,
                                        float* __restrict__ X, int lane, int nth)
{
    for (int e = lane; e < 512; e += nth) {
        float v = A[72 + e] + B[72 + e];
        v = fmaf(A[e >> 6],       B[8 + (e & 63)], v);
        v = fmaf(A[8 + (e >> 3)], B[e & 7],        v);
        X[72 + e] = v;
    }
}
__device__ __forceinline__ void chen_inplace(float* __restrict__ A,
                                             const float* __restrict__ B,
                                             int lane, int nth)
{
    chen_l4(A, B, A, lane, nth);      // reads A[0..584), writes A[584..)
    __syncthreads();
    chen_l3(A, B, A, lane, nth);      // reads A[0..72), writes A[72..584)
    float v2 = 0.0f, v1 = 0.0f;
    if (lane < 64) v2 = A[8 + lane] + B[8 + lane] + A[lane >> 3] * B[lane & 7];
    if (lane < 8)  v1 = A[lane] + B[lane];
    __syncthreads();
    if (lane < 64) A[8 + lane] = v2;
    if (lane < 8)  A[lane] = v1;
}

// ---------------------------------------------------------------------------
// Kernel 1: segmented scan. 1 CTA/batch, 512 threads = 8 groups x 64.
// Thread u=tid&63 owns (a,b)=(u>>3,u&7): all 8 c, all 8 d (64 L4 accumulators).
// ---------------------------------------------------------------------------
__global__ __launch_bounds__(512, 1) void sig_scan_kernel(const float* __restrict__ inp)
{
    extern __shared__ float sm[];
    const int b   = blockIdx.x;
    const int tid = threadIdx.x;

    // Build increments into sm[0..8192). Basepoint 0: first inc = first sample.
    const float dt = 1.0f / 1023.0f;
    const float* x = inp + (size_t)b * SLEN * CIN;
    for (int i = tid; i < SLEN * CIN; i += 512) {
        int t = i / CIN, c = i - t * CIN;
        float cur  = x[i];
        float prev = (t == 0) ? 0.0f : x[i - CIN];
        sm[t * 8 + c + 1] = cur - prev;
    }
    for (int t = tid; t < SLEN; t += 512)
        sm[t * 8] = (t == 0) ? 0.0f : dt;
    __syncthreads();

    const int g  = tid >> 6;          // segment 0..7
    const int u  = tid & 63;          // (a,b)
    const int a  = u >> 3;
    const int bb = u & 7;

    float s1 = 0.0f, s2 = 0.0f;
    float s3[8];
    float sig4[64];
#pragma unroll
    for (int i = 0; i < 8; i++) s3[i] = 0.0f;
#pragma unroll
    for (int i = 0; i < 64; i++) sig4[i] = 0.0f;

    const float inv24 = 1.0f / 24.0f;
    const float inv6  = 1.0f / 6.0f;
    const float* vrow = sm + g * SEG * 8;

#pragma unroll 1
    for (int t = 0; t < SEG; t++) {
        float vv[8];
        *(float4*)&vv[0] = *(const float4*)&vrow[t * 8];
        *(float4*)&vv[4] = *(const float4*)&vrow[t * 8 + 4];
        // Runtime-offset reads come from SHARED (LDS), never from the register
        // array: vv[a] would force vv into local memory.
        float va = vrow[t * 8 + a];
        float vb = vrow[t * 8 + bb];

        // All derived from OLD s1,s2,s3.
        float t6 = fmaf(s1, inv6, va * inv24);   // va/24 + s1/6
        float uu = fmaf(s1, 0.5f, va * inv6);    // va/6  + s1/2
        float m1 = fmaf(vb, t6, s2 * 0.5f);      // vb*t6 + s2/2
        float m2 = fmaf(vb, uu, s2);             // vb*uu + s2

        float K[8];
#pragma unroll
        for (int c = 0; c < 8; c++) {
            K[c]  = fmaf(vv[c], m1, s3[c]);
            s3[c] = fmaf(vv[c], m2, s3[c]);
        }
#pragma unroll
        for (int c = 0; c < 8; c++)
#pragma unroll
            for (int d = 0; d < 8; d++)
                sig4[c * 8 + d] = fmaf(K[c], vv[d], sig4[c * 8 + d]);

        s2 = fmaf(vb, fmaf(va, 0.5f, s1), s2);   // s2 + va*vb/2 + s1*vb
        s1 += va;
    }

    // All scan reads of sm done -> safe to overwrite with T[8][4680].
    __syncthreads();

    // Fully unrolled write-out: every sig4 index is a compile-time constant.
    float* P = sm + g * SIGCH;
#pragma unroll
    for (int c = 0; c < 8; c++) {
#pragma unroll
        for (int d = 0; d < 8; d++)
            P[584 + u * 64 + c * 8 + d] = sig4[c * 8 + d];
        P[72 + u * 8 + c] = s3[c];
    }
    P[8 + u] = s2;
    if (bb == 0) P[a] = s1;
    __syncthreads();

    // Round 1: 4 parallel in-place combines, 128 threads each.
    {
        int pair = tid >> 7, lane = tid & 127;
        float* A = sm + (2 * pair) * SIGCH;
        const float* B = A + SIGCH;
        chen_inplace(A, B, lane, 128);
    }
    __syncthreads();
    // Round 2: 2 parallel in-place combines, 256 threads each.
    {
        int pair = tid >> 8, lane = tid & 255;
        float* A = sm + (4 * pair) * SIGCH;
        const float* B = A + 2 * SIGCH;
        chen_inplace(A, B, lane, 256);
    }
    __syncthreads();
    // Round 3: final combine straight to global.
    {
        const float* A = sm;
        const float* B = sm + 4 * SIGCH;
        float* y = g_y + (size_t)b * YSTRIDE;
        chen_l4(A, B, y, tid, 512);
        chen_l3(A, B, y, tid, 512);
        if (tid < 64) y[8 + tid] = A[8 + tid] + B[8 + tid] + A[tid >> 3] * B[tid & 7];
        if (tid < 8)  y[tid] = A[tid] + B[tid];
        if (tid < YSTRIDE - SIGCH) y[SIGCH + tid] = 0.0f;   // 56 pad elems
    }
}

// ---------------------------------------------------------------------------
// Kernel 2: split-k GEMM partials. grid = (8 col-groups, KSPLIT=37) = 296 CTAs
// = exactly 2 resident CTAs on each of 148 SMs (one balanced wave).
// CTA: 128 batch-rows x 32 out-cols over 128 of k. 256 threads, 16 accums.
// ws stored transposed [k][col]; 36-float pitch keeps reads conflict-free.
// ---------------------------------------------------------------------------
__global__ __launch_bounds__(256, 2) void gemm_part_kernel(const float* __restrict__ W)
{
    __shared__ float ys[128][36];
    __shared__ float ws[32][36];    // [k][col]

    const int tid = threadIdx.x;
    const int cg = blockIdx.x;      // cols cg*32 .. cg*32+31
    const int sp = blockIdx.y;      // k in [sp*128, sp*128+128)
    const int kbase = sp * KCHUNK;

    const int cp = tid & 7;         // cols 4cp .. 4cp+3
    const int rg = tid >> 3;        // rows rg + 32*j, j<4

    float acc[4][4];
#pragma unroll
    for (int i = 0; i < 4; i++)
#pragma unroll
        for (int j = 0; j < 4; j++) acc[i][j] = 0.0f;

    for (int kc = 0; kc < KCHUNK; kc += 32) {
        const int k0 = kbase + kc;
        // y tile: 128 x 32
#pragma unroll
        for (int ii = 0; ii < 4; ii++) {
            int lin = tid + 256 * ii;
            int r = lin >> 3, seg = lin & 7;
            float4 val = *(const float4*)&g_y[r * YSTRIDE + k0 + seg * 4];
            *(float4*)&ys[r][seg * 4] = val;
        }
        // W tile transposed: ws[k][col] = W[cg*32+col][k0+k]; guard k >= SIGCH.
#pragma unroll
        for (int ii = 0; ii < 4; ii++) {
            int lin = tid + 256 * ii;        // 0..1023
            int col = lin >> 5, k = lin & 31;
            int kg = k0 + k;
            ws[k][col] = (kg < SIGCH) ? W[(cg * 32 + col) * SIGCH + kg] : 0.0f;
        }
        __syncthreads();
#pragma unroll
        for (int kk = 0; kk < 32; kk += 2) {
            float4 wA = *(const float4*)&ws[kk][4 * cp];
            float4 wB = *(const float4*)&ws[kk + 1][4 * cp];
            float2 y0 = *(const float2*)&ys[rg][kk];
            float2 y1 = *(const float2*)&ys[rg + 32][kk];
            float2 y2 = *(const float2*)&ys[rg + 64][kk];
            float2 y3 = *(const float2*)&ys[rg + 96][kk];
            acc[0][0] = fmaf(y0.x, wA.x, acc[0][0]); acc[0][0] = fmaf(y0.y, wB.x, acc[0][0]);
            acc[0][1] = fmaf(y0.x, wA.y, acc[0][1]); acc[0][1] = fmaf(y0.y, wB.y, acc[0][1]);
            acc[0][2] = fmaf(y0.x, wA.z, acc[0][2]); acc[0][2] = fmaf(y0.y, wB.z, acc[0][2]);
            acc[0][3] = fmaf(y0.x, wA.w, acc[0][3]); acc[0][3] = fmaf(y0.y, wB.w, acc[0][3]);
            acc[1][0] = fmaf(y1.x, wA.x, acc[1][0]); acc[1][0] = fmaf(y1.y, wB.x, acc[1][0]);
            acc[1][1] = fmaf(y1.x, wA.y, acc[1][1]); acc[1][1] = fmaf(y1.y, wB.y, acc[1][1]);
            acc[1][2] = fmaf(y1.x, wA.z, acc[1][2]); acc[1][2] = fmaf(y1.y, wB.z, acc[1][2]);
            acc[1][3] = fmaf(y1.x, wA.w, acc[1][3]); acc[1][3] = fmaf(y1.y, wB.w, acc[1][3]);
            acc[2][0] = fmaf(y2.x, wA.x, acc[2][0]); acc[2][0] = fmaf(y2.y, wB.x, acc[2][0]);
            acc[2][1] = fmaf(y2.x, wA.y, acc[2][1]); acc[2][1] = fmaf(y2.y, wB.y, acc[2][1]);
            acc[2][2] = fmaf(y2.x, wA.z, acc[2][2]); acc[2][2] = fmaf(y2.y, wB.z, acc[2][2]);
            acc[2][3] = fmaf(y2.x, wA.w, acc[2][3]); acc[2][3] = fmaf(y2.y, wB.w, acc[2][3]);
            acc[3][0] = fmaf(y3.x, wA.x, acc[3][0]); acc[3][0] = fmaf(y3.y, wB.x, acc[3][0]);
            acc[3][1] = fmaf(y3.x, wA.y, acc[3][1]); acc[3][1] = fmaf(y3.y, wB.y, acc[3][1]);
            acc[3][2] = fmaf(y3.x, wA.z, acc[3][2]); acc[3][2] = fmaf(y3.y, wB.z, acc[3][2]);
            acc[3][3] = fmaf(y3.x, wA.w, acc[3][3]); acc[3][3] = fmaf(y3.y, wB.w, acc[3][3]);
        }
        __syncthreads();
    }

    const int col0 = cg * 32 + 4 * cp;
    float* p = g_part + (size_t)sp * NB * DOUT;
#pragma unroll
    for (int i = 0; i < 4; i++) {
        float4 v = make_float4(acc[i][0], acc[i][1], acc[i][2], acc[i][3]);
        *(float4*)&p[(rg + 32 * i) * DOUT + col0] = v;
    }
}

// ---------------------------------------------------------------------------
__global__ void reduce_bias_kernel(const float* __restrict__ bias, float* __restrict__ out)
{
    int idx = blockIdx.x * 256 + threadIdx.x;
    float v = bias[idx & (DOUT - 1)];
#pragma unroll
    for (int s = 0; s < KSPLIT; s++)
        v += g_part[s * NB * DOUT + idx];
    out[idx] = v;
}

// ---------------------------------------------------------------------------
extern "C" void kernel_launch(void* const* d_in, const int* in_sizes, int n_in,
                              void* d_out, int out_size)
{
    (void)in_sizes; (void)n_in; (void)out_size;
    const float* inp  = (const float*)d_in[0];   // (128,1024,7)
    const float* W    = (const float*)d_in[1];   // (256,4680)
    const float* bias = (const float*)d_in[2];   // (256,)
    float* out = (float*)d_out;                  // (128,256)

    const int smem_bytes = SMEM_FLOATS * sizeof(float);   // 149760
    cudaFuncSetAttribute(sig_scan_kernel,
                         cudaFuncAttributeMaxDynamicSharedMemorySize, smem_bytes);

    sig_scan_kernel<<<NB, 512, smem_bytes>>>(inp);
    dim3 g2(8, KSPLIT);
    gemm_part_kernel<<<g2, 256>>>(W);
    reduce_bias_kernel<<<NB, 256>>>(bias, out);
}